// round 16
// baseline (speedup 1.0000x reference)
#include <cuda_runtime.h>
#include <math.h>

// ---------------------------------------------------------------------------
// SpectralNorm: out = conv2d(x, w_bar, pad=1) * (1/sigma) + bias
// sigma = max(1, s_max(w_bar.view(32,288)) / 2)
// Shapes: x[32,32,256,256] f32, w_bar[32,32,3,3] f32, bias[32] f32
// ---------------------------------------------------------------------------

__device__ float g_inv_sigma;

// ---------------------------------------------------------------------------
// Kernel 1: largest singular value via G = W W^T, 15 trace-normalized
// squarings (power 2^15), then Rayleigh quotient v^T G v / v^T v.
// One block, 1024 threads; thread (i,j) owns G[i][j].
// ---------------------------------------------------------------------------
__global__ void sigma_kernel(const float* __restrict__ wb) {
    __shared__ float G[32][32];
    __shared__ float A[32][32];
    __shared__ float Bm[32][32];
    __shared__ float tr_s;
    __shared__ float vvec[32];
    __shared__ float gvec[32];

    int tid = threadIdx.x;
    int i = tid >> 5, j = tid & 31;

    // G[i][j] = <row_i, row_j>, rows of length 288 (16B aligned: 288*4=1152)
    const float4* ri = reinterpret_cast<const float4*>(wb + i * 288);
    const float4* rj = reinterpret_cast<const float4*>(wb + j * 288);
    float s = 0.f;
#pragma unroll 8
    for (int m = 0; m < 72; ++m) {
        float4 a = ri[m], b = rj[m];
        s += a.x * b.x + a.y * b.y + a.z * b.z + a.w * b.w;
    }
    G[i][j] = s;
    __syncthreads();

    if (tid == 0) {
        float t = 0.f;
        for (int k = 0; k < 32; ++k) t += G[k][k];
        tr_s = t;
    }
    __syncthreads();
    A[i][j] = G[i][j] / tr_s;
    __syncthreads();

    // 15 squarings with trace normalization: final matrix ~ u u^T
    for (int it = 0; it < 15; ++it) {
        const float (*S)[32] = (it & 1) ? Bm : A;
        float (*D)[32] = (it & 1) ? A : Bm;
        float acc = 0.f;
#pragma unroll
        for (int k = 0; k < 32; ++k) acc += S[i][k] * S[k][j];
        __syncthreads();          // all reads of S complete
        D[i][j] = acc;
        __syncthreads();
        if (tid == 0) {
            float t = 0.f;
            for (int k = 0; k < 32; ++k) t += D[k][k];
            tr_s = t;
        }
        __syncthreads();
        D[i][j] = D[i][j] / tr_s;
        __syncthreads();
    }

    // Final matrix after it=14 lives in Bm. v = F @ ones (generic vector in
    // the top eigenspace), then lambda_1 = (v^T G v)/(v^T v).
    const float (*F)[32] = Bm;
    if (j == 0) {
        float t = 0.f;
        for (int k = 0; k < 32; ++k) t += F[i][k];
        vvec[i] = t;
    }
    __syncthreads();
    if (j == 0) {
        float t = 0.f;
        for (int k = 0; k < 32; ++k) t += G[i][k] * vvec[k];
        gvec[i] = t;
    }
    __syncthreads();
    if (tid == 0) {
        float num = 0.f, den = 0.f;
        for (int k = 0; k < 32; ++k) {
            num += vvec[k] * gvec[k];
            den += vvec[k] * vvec[k];
        }
        float lam = num / den;
        float smax = sqrtf(fmaxf(lam, 0.f));
        float sigma = fmaxf(1.f, smax * 0.5f);
        g_inv_sigma = 1.f / sigma;
    }
}

// ---------------------------------------------------------------------------
// Kernel 2: 3x3 conv, register-blocked implicit form.
// Block: one n, 8 output rows x 64 output cols, all 32 output channels.
// Thread (h = warp id 0..7; lane: kg=lane/8 0..3, wg=lane%8 0..7):
//   8 output channels (kg*8..+8) x 8 cols (wg*8..+8) on row h -> 64 accs.
// C processed in 4 chunks of 8 to keep static smem < 48KB (2 blocks/SM).
// Epilogue scales by 1/sigma (conv linear in w) and adds bias.
// ---------------------------------------------------------------------------
__global__ __launch_bounds__(256, 2)
void conv_kernel(const float* __restrict__ x, const float* __restrict__ wb,
                 const float* __restrict__ bias, float* __restrict__ out) {
    __shared__ float xs[8][10][68];   // 8 c x (8+2) rows x (64+2 -> pad 68) cols
    __shared__ float ws[72][32];      // [ (c'*3+r)*3+s ][ k ]  (128B rows)

    const int tid = threadIdx.x;
    const int h  = tid >> 5;          // warp id = output row within tile
    const int kg = (tid >> 3) & 3;    // k group
    const int wg = tid & 7;           // col group

    const int wt = blockIdx.x;        // 0..3   (64-col tiles)
    const int ht = blockIdx.y;        // 0..31  (8-row tiles)
    const int n  = blockIdx.z;        // 0..31

    const int gh0 = ht * 8 - 1;
    const int gw0 = wt * 64 - 1;
    const float* xn = x + (size_t)n * 32 * 65536;

    float acc[8][8];
#pragma unroll
    for (int a = 0; a < 8; ++a)
#pragma unroll
        for (int b = 0; b < 8; ++b) acc[a][b] = 0.f;

    for (int cc = 0; cc < 4; ++cc) {
        __syncthreads();  // previous chunk's compute done before overwrite

        // --- stage x chunk: channels cc*8 .. cc*8+7, 10x66 halo tile ---
        for (int idx = tid; idx < 8 * 10 * 66; idx += 256) {
            int cp  = idx / 660;
            int rem = idx - cp * 660;
            int hh  = rem / 66;
            int ww  = rem - hh * 66;
            int gh = gh0 + hh, gw = gw0 + ww;
            float v = 0.f;
            if ((unsigned)gh < 256u && (unsigned)gw < 256u)
                v = xn[(size_t)(cc * 8 + cp) * 65536 + gh * 256 + gw];
            xs[cp][hh][ww] = v;
        }
        // --- stage w chunk: 8 c x 9 taps x 32 k, transposed to [crs][k] ---
        for (int idx = tid; idx < 2304; idx += 256) {
            int t = idx >> 5;         // 0..71 = c'*9 + r*3 + s
            int k = idx & 31;
            ws[t][k] = wb[k * 288 + cc * 72 + t];
        }
        __syncthreads();

        // --- compute ---
#pragma unroll
        for (int cp = 0; cp < 8; ++cp) {
#pragma unroll
            for (int r = 0; r < 3; ++r) {
                const float* xr = &xs[cp][h + r][wg * 8];
                float4 a0 = *reinterpret_cast<const float4*>(xr);
                float4 a1 = *reinterpret_cast<const float4*>(xr + 4);
                float2 a2 = *reinterpret_cast<const float2*>(xr + 8);
                float xv[10] = {a0.x, a0.y, a0.z, a0.w,
                                a1.x, a1.y, a1.z, a1.w,
                                a2.x, a2.y};
#pragma unroll
                for (int s = 0; s < 3; ++s) {
                    const float* wp = &ws[(cp * 3 + r) * 3 + s][kg * 8];
                    float4 w0 = *reinterpret_cast<const float4*>(wp);
                    float4 w1 = *reinterpret_cast<const float4*>(wp + 4);
                    float wv[8] = {w0.x, w0.y, w0.z, w0.w,
                                   w1.x, w1.y, w1.z, w1.w};
#pragma unroll
                    for (int kk = 0; kk < 8; ++kk)
#pragma unroll
                        for (int jj = 0; jj < 8; ++jj)
                            acc[kk][jj] += wv[kk] * xv[jj + s];
                }
            }
        }
    }

    // --- epilogue: scale by 1/sigma, add bias, vectorized store ---
    const float inv_sigma = g_inv_sigma;
    const int row  = ht * 8 + h;
    const int col0 = wt * 64 + wg * 8;
#pragma unroll
    for (int kk = 0; kk < 8; ++kk) {
        int k = kg * 8 + kk;
        float b = bias[k];
        float* op = out + (((size_t)n * 32 + k) * 65536 + (size_t)row * 256 + col0);
        float4 o0, o1;
        o0.x = acc[kk][0] * inv_sigma + b;
        o0.y = acc[kk][1] * inv_sigma + b;
        o0.z = acc[kk][2] * inv_sigma + b;
        o0.w = acc[kk][3] * inv_sigma + b;
        o1.x = acc[kk][4] * inv_sigma + b;
        o1.y = acc[kk][5] * inv_sigma + b;
        o1.z = acc[kk][6] * inv_sigma + b;
        o1.w = acc[kk][7] * inv_sigma + b;
        *reinterpret_cast<float4*>(op)     = o0;
        *reinterpret_cast<float4*>(op + 4) = o1;
    }
}

// ---------------------------------------------------------------------------
extern "C" void kernel_launch(void* const* d_in, const int* in_sizes, int n_in,
                              void* d_out, int out_size) {
    const float* x    = (const float*)d_in[0];
    const float* wb   = (const float*)d_in[1];
    const float* bias = (const float*)d_in[2];
    float* out = (float*)d_out;

    sigma_kernel<<<1, 1024>>>(wb);

    dim3 grid(4, 32, 32);   // (w tiles, h tiles, n)
    conv_kernel<<<grid, 256>>>(x, wb, bias, out);
}

// round 17
// speedup vs baseline: 1.1773x; 1.1773x over previous
#include <cuda_runtime.h>
#include <math.h>

// ---------------------------------------------------------------------------
// SpectralNorm: out = conv2d(x, w_bar, pad=1) * (1/sigma) + bias
// sigma = max(1, s_max(w_bar.view(32,288)) / 2)
// Shapes: x[32,32,256,256] f32, w_bar[32,32,3,3] f32, bias[32] f32
//
// R16: inner loop rewritten with packed fma.rn.f32x2 (Blackwell FFMA2).
// Scalar FFMA is issue-rate bound at 2 warp-instr/cyc/SM (rt_SMSP=2); the
// packed form does 2 MACs per slot. Accumulators pair adjacent output
// channels so the w-operand pair is a single aligned LDS.64 from ws[][].
// ---------------------------------------------------------------------------

__device__ float g_inv_sigma;

#define FMA2(acc, a, b) \
    asm("fma.rn.f32x2 %0, %1, %2, %0;" : "+l"(acc) : "l"(a), "l"(b))
#define DUP2(d, v) \
    asm("mov.b64 %0, {%1, %1};" : "=l"(d) : "r"(__float_as_uint(v)))
#define UNPACK2(lo, hi, v) \
    asm("mov.b64 {%0, %1}, %2;" : "=r"(lo), "=r"(hi) : "l"(v))

// ---------------------------------------------------------------------------
// Kernel 1: largest singular value via G = W W^T, 15 trace-normalized
// squarings (power 2^15), then Rayleigh quotient v^T G v / v^T v.
// ---------------------------------------------------------------------------
__global__ void sigma_kernel(const float* __restrict__ wb) {
    __shared__ float G[32][32];
    __shared__ float A[32][32];
    __shared__ float Bm[32][32];
    __shared__ float tr_s;
    __shared__ float vvec[32];
    __shared__ float gvec[32];

    int tid = threadIdx.x;
    int i = tid >> 5, j = tid & 31;

    const float4* ri = reinterpret_cast<const float4*>(wb + i * 288);
    const float4* rj = reinterpret_cast<const float4*>(wb + j * 288);
    float s = 0.f;
#pragma unroll 8
    for (int m = 0; m < 72; ++m) {
        float4 a = ri[m], b = rj[m];
        s += a.x * b.x + a.y * b.y + a.z * b.z + a.w * b.w;
    }
    G[i][j] = s;
    __syncthreads();

    if (tid == 0) {
        float t = 0.f;
        for (int k = 0; k < 32; ++k) t += G[k][k];
        tr_s = t;
    }
    __syncthreads();
    A[i][j] = G[i][j] / tr_s;
    __syncthreads();

    for (int it = 0; it < 15; ++it) {
        const float (*S)[32] = (it & 1) ? Bm : A;
        float (*D)[32] = (it & 1) ? A : Bm;
        float acc = 0.f;
#pragma unroll
        for (int k = 0; k < 32; ++k) acc += S[i][k] * S[k][j];
        __syncthreads();
        D[i][j] = acc;
        __syncthreads();
        if (tid == 0) {
            float t = 0.f;
            for (int k = 0; k < 32; ++k) t += D[k][k];
            tr_s = t;
        }
        __syncthreads();
        D[i][j] = D[i][j] / tr_s;
        __syncthreads();
    }

    const float (*F)[32] = Bm;
    if (j == 0) {
        float t = 0.f;
        for (int k = 0; k < 32; ++k) t += F[i][k];
        vvec[i] = t;
    }
    __syncthreads();
    if (j == 0) {
        float t = 0.f;
        for (int k = 0; k < 32; ++k) t += G[i][k] * vvec[k];
        gvec[i] = t;
    }
    __syncthreads();
    if (tid == 0) {
        float num = 0.f, den = 0.f;
        for (int k = 0; k < 32; ++k) {
            num += vvec[k] * gvec[k];
            den += vvec[k] * vvec[k];
        }
        float lam = num / den;
        float smax = sqrtf(fmaxf(lam, 0.f));
        float sigma = fmaxf(1.f, smax * 0.5f);
        g_inv_sigma = 1.f / sigma;
    }
}

// ---------------------------------------------------------------------------
// Kernel 2: 3x3 conv, register-blocked, packed-f32x2 inner loop.
// Block: one n, 8 output rows x 64 output cols, all 32 output channels.
// Thread (h = warp id 0..7; lane: kg=lane/8, wg=lane%8):
//   8 output channels (kg*8..+8, paired -> 4 f32x2) x 8 cols on row h.
// ---------------------------------------------------------------------------
__global__ __launch_bounds__(256, 2)
void conv_kernel(const float* __restrict__ x, const float* __restrict__ wb,
                 const float* __restrict__ bias, float* __restrict__ out) {
    __shared__ float xs[8][10][68];   // 8 c x (8+2) rows x (64+2 -> pad 68) cols
    __shared__ float ws[72][32];      // [ (c'*3+r)*3+s ][ k ]  (128B rows)

    const int tid = threadIdx.x;
    const int h  = tid >> 5;          // warp id = output row within tile
    const int kg = (tid >> 3) & 3;    // k group (8 channels)
    const int wg = tid & 7;           // col group (8 cols)

    const int wt = blockIdx.x;        // 0..3   (64-col tiles)
    const int ht = blockIdx.y;        // 0..31  (8-row tiles)
    const int n  = blockIdx.z;        // 0..31

    const int gh0 = ht * 8 - 1;
    const int gw0 = wt * 64 - 1;
    const float* xn = x + (size_t)n * 32 * 65536;

    // acc2[kk2][jj]: packed pair of channels (kg*8+2*kk2, +1), column jj
    unsigned long long acc2[4][8];
#pragma unroll
    for (int a = 0; a < 4; ++a)
#pragma unroll
        for (int b = 0; b < 8; ++b) acc2[a][b] = 0ull;

    for (int cc = 0; cc < 4; ++cc) {
        __syncthreads();  // previous chunk's compute done before overwrite

        // --- stage x chunk: channels cc*8 .. cc*8+7, 10x66 halo tile ---
        for (int idx = tid; idx < 8 * 10 * 66; idx += 256) {
            int cp  = idx / 660;
            int rem = idx - cp * 660;
            int hh  = rem / 66;
            int ww  = rem - hh * 66;
            int gh = gh0 + hh, gw = gw0 + ww;
            float v = 0.f;
            if ((unsigned)gh < 256u && (unsigned)gw < 256u)
                v = xn[(size_t)(cc * 8 + cp) * 65536 + gh * 256 + gw];
            xs[cp][hh][ww] = v;
        }
        // --- stage w chunk: 8 c x 9 taps x 32 k, transposed to [crs][k] ---
        for (int idx = tid; idx < 2304; idx += 256) {
            int t = idx >> 5;         // 0..71 = c'*9 + r*3 + s
            int k = idx & 31;
            ws[t][k] = wb[k * 288 + cc * 72 + t];
        }
        __syncthreads();

        // --- compute ---
#pragma unroll
        for (int cp = 0; cp < 8; ++cp) {
#pragma unroll
            for (int r = 0; r < 3; ++r) {
                const float* xr = &xs[cp][h + r][wg * 8];
                float4 a0 = *reinterpret_cast<const float4*>(xr);
                float4 a1 = *reinterpret_cast<const float4*>(xr + 4);
                float2 a2 = *reinterpret_cast<const float2*>(xr + 8);
                // broadcast-duplicated packs of the 10 x values
                unsigned long long xb[10];
                DUP2(xb[0], a0.x); DUP2(xb[1], a0.y);
                DUP2(xb[2], a0.z); DUP2(xb[3], a0.w);
                DUP2(xb[4], a1.x); DUP2(xb[5], a1.y);
                DUP2(xb[6], a1.z); DUP2(xb[7], a1.w);
                DUP2(xb[8], a2.x); DUP2(xb[9], a2.y);
#pragma unroll
                for (int s = 0; s < 3; ++s) {
                    // 4 packed channel-pairs, single aligned LDS.64 each
                    const unsigned long long* wp =
                        reinterpret_cast<const unsigned long long*>(
                            &ws[(cp * 3 + r) * 3 + s][kg * 8]);
                    unsigned long long w0 = wp[0];
                    unsigned long long w1 = wp[1];
                    unsigned long long w2 = wp[2];
                    unsigned long long w3 = wp[3];
#pragma unroll
                    for (int jj = 0; jj < 8; ++jj) {
                        unsigned long long xv = xb[jj + s];
                        FMA2(acc2[0][jj], w0, xv);
                        FMA2(acc2[1][jj], w1, xv);
                        FMA2(acc2[2][jj], w2, xv);
                        FMA2(acc2[3][jj], w3, xv);
                    }
                }
            }
        }
    }

    // --- epilogue: unpack, scale by 1/sigma, add bias, vectorized store ---
    const float inv_sigma = g_inv_sigma;
    const int row  = ht * 8 + h;
    const int col0 = wt * 64 + wg * 8;
#pragma unroll
    for (int kk2 = 0; kk2 < 4; ++kk2) {
        int k0 = kg * 8 + kk2 * 2;
        float b0 = bias[k0];
        float b1 = bias[k0 + 1];
        float lo[8], hi[8];
#pragma unroll
        for (int jj = 0; jj < 8; ++jj) {
            unsigned int l, hgh;
            UNPACK2(l, hgh, acc2[kk2][jj]);
            lo[jj] = __uint_as_float(l);
            hi[jj] = __uint_as_float(hgh);
        }
        float* op0 = out + (((size_t)n * 32 + k0) * 65536 +
                            (size_t)row * 256 + col0);
        float* op1 = op0 + 65536;
        float4 o;
        o.x = lo[0] * inv_sigma + b0; o.y = lo[1] * inv_sigma + b0;
        o.z = lo[2] * inv_sigma + b0; o.w = lo[3] * inv_sigma + b0;
        *reinterpret_cast<float4*>(op0) = o;
        o.x = lo[4] * inv_sigma + b0; o.y = lo[5] * inv_sigma + b0;
        o.z = lo[6] * inv_sigma + b0; o.w = lo[7] * inv_sigma + b0;
        *reinterpret_cast<float4*>(op0 + 4) = o;
        o.x = hi[0] * inv_sigma + b1; o.y = hi[1] * inv_sigma + b1;
        o.z = hi[2] * inv_sigma + b1; o.w = hi[3] * inv_sigma + b1;
        *reinterpret_cast<float4*>(op1) = o;
        o.x = hi[4] * inv_sigma + b1; o.y = hi[5] * inv_sigma + b1;
        o.z = hi[6] * inv_sigma + b1; o.w = hi[7] * inv_sigma + b1;
        *reinterpret_cast<float4*>(op1 + 4) = o;
    }
}

// ---------------------------------------------------------------------------
extern "C" void kernel_launch(void* const* d_in, const int* in_sizes, int n_in,
                              void* d_out, int out_size) {
    const float* x    = (const float*)d_in[0];
    const float* wb   = (const float*)d_in[1];
    const float* bias = (const float*)d_in[2];
    float* out = (float*)d_out;

    sigma_kernel<<<1, 1024>>>(wb);

    dim3 grid(4, 32, 32);   // (w tiles, h tiles, n)
    conv_kernel<<<grid, 256>>>(x, wb, bias, out);
}